// round 1
// baseline (speedup 1.0000x reference)
#include <cuda_runtime.h>

// Problem constants (fixed by the reference)
#define Lr    512
#define Bb    16
#define Cc    4
#define NLAY  4
#define HIDN  256
#define HROWS 32              // output rows per CTA
#define TROWS 48              // tile rows = HROWS + 2*8 halo (4 layers * radius 2)
#define NBLK  (Lr / HROWS)    // 16 row blocks

// Scratch: sep[b][c][r]  (B*C*L floats = 128KB) — device global, no allocs.
__device__ float g_sep[Bb * Cc * Lr];

__device__ __forceinline__ float celu_f(float v) {
    // jax.nn.celu, alpha=1: v>0 ? v : expm1(v)
    return v > 0.f ? v : (__expf(v) - 1.f);
}

__global__ void zero_sep_kernel() {
    int i = blockIdx.x * blockDim.x + threadIdx.x;
    if (i < Bb * Cc * Lr) g_sep[i] = 0.f;
}

// Dynamic smem layout:
//  buf0 [TROWS*Lr] | buf1 [TROWS*Lr] | nx[Lr] | ny[Lr] | nz[Lr]
#define SMEM_FLOATS (2 * TROWS * Lr + 3 * Lr)

extern __shared__ float s_mem[];

__global__ __launch_bounds__(512, 1)
void fused_layers_kernel(const float* __restrict__ n,
                         const float* __restrict__ w_self,
                         const float* __restrict__ w_nbr)
{
    const int j   = threadIdx.x;      // column 0..511
    const int blk = blockIdx.x;       // row block
    const int c   = blockIdx.y;
    const int b   = blockIdx.z;

    float* buf0 = s_mem;
    float* buf1 = s_mem + TROWS * Lr;
    float* nsx  = s_mem + 2 * TROWS * Lr;
    float* nsy  = nsx + Lr;
    float* nsz  = nsx + 2 * Lr;

    // Load n[b] (512 x 3) into smem
    {
        const float* base = n + (size_t)b * Lr * 3;
        nsx[j] = base[j * 3 + 0];
        nsy[j] = base[j * 3 + 1];
        nsz[j] = base[j * 3 + 2];
    }
    __syncthreads();

    const int r0 = blk * HROWS - 8;   // global row of tile row 0 (mod 512)
    const float njx = nsx[j], njy = nsy[j], njz = nsz[j];

    // Build layer-0 input (masked Gram) directly in smem — no HBM materialization.
    #pragma unroll 4
    for (int t = 0; t < TROWS; ++t) {
        int gr = (r0 + t) & (Lr - 1);
        float g = njx * nsx[gr] + njy * nsy[gr] + njz * nsz[gr];
        if (gr == j) g = 0.f;
        buf0[t * Lr + j] = g;
    }
    __syncthreads();

    const int jm1 = (j - 1) & (Lr - 1), jp1 = (j + 1) & (Lr - 1);
    const int jm2 = (j - 2) & (Lr - 1), jp2 = (j + 2) & (Lr - 1);

    float* src = buf0;
    float* dst = buf1;

    for (int ell = 0; ell < NLAY; ++ell) {
        const float ws  = w_self[c * NLAY + ell];
        const float wn0 = w_nbr[(c * NLAY + ell) * 2 + 0];
        const float wn1 = w_nbr[(c * NLAY + ell) * 2 + 1];
        const int lo = 2 + 2 * ell;
        const int hi = (TROWS - 3) - 2 * ell;   // 45 - 2*ell

        // vertical sliding window (rows i-2..i+1) in registers: 1 new LDS per row
        float wm2 = src[(lo - 2) * Lr + j];
        float wm1 = src[(lo - 1) * Lr + j];
        float w0  = src[(lo    ) * Lr + j];
        float wp1 = src[(lo + 1) * Lr + j];

        #pragma unroll 4
        for (int i = lo; i <= hi; ++i) {
            float wp2 = src[(i + 2) * Lr + j];
            const float* row = src + i * Lr;
            float l1 = row[jm1], r1 = row[jp1];
            float l2 = row[jm2], r2 = row[jp2];
            float y = ws * w0 + wn0 * (wm1 + wp1 + l1 + r1)
                              + wn1 * (wm2 + wp2 + l2 + r2);
            float nv = w0 + celu_f(y);
            int gr = (r0 + i) & (Lr - 1);
            if (gr == j) nv = 0.f;               // diagonal mask (symmetrize is a no-op)
            dst[i * Lr + j] = nv;
            wm2 = wm1; wm1 = w0; w0 = wp1; wp1 = wp2;
        }
        __syncthreads();
        float* tmp = src; src = dst; dst = tmp;
    }

    // sep[r] = sum_i x[i, (i+r) mod L]; thread j owns r=j, register accumulator.
    float acc = 0.f;
    #pragma unroll 8
    for (int t = 8; t < 8 + HROWS; ++t) {
        int gr = r0 + t;                          // = blk*32 + (t-8), in [0,511]
        acc += src[t * Lr + ((gr + j) & (Lr - 1))];
    }
    atomicAdd(&g_sep[(b * Cc + c) * Lr + j], acc);
}

__global__ __launch_bounds__(HIDN)
void mlp_kernel(const float* __restrict__ W1, const float* __restrict__ b1,
                const float* __restrict__ W2, const float* __restrict__ b2,
                float* __restrict__ out)
{
    __shared__ float s[Cc * Lr];      // 2048 floats
    __shared__ float hred[HIDN];
    const int b = blockIdx.x, t = threadIdx.x;

    for (int k = t; k < Cc * Lr; k += HIDN) s[k] = g_sep[b * Cc * Lr + k];
    __syncthreads();

    float acc = b1[t];
    #pragma unroll 8
    for (int k = 0; k < Cc * Lr; ++k)
        acc = fmaf(s[k], W1[k * HIDN + t], acc);   // W1 coalesced across t, s[k] broadcast
    float h = celu_f(acc);
    hred[t] = h * W2[t];
    __syncthreads();
    for (int off = HIDN / 2; off > 0; off >>= 1) {
        if (t < off) hred[t] += hred[t + off];
        __syncthreads();
    }
    if (t == 0) out[b] = __expf(-(hred[0] + b2[0]));
}

extern "C" void kernel_launch(void* const* d_in, const int* in_sizes, int n_in,
                              void* d_out, int out_size)
{
    const float* n      = (const float*)d_in[0];
    const float* w_self = (const float*)d_in[1];
    const float* w_nbr  = (const float*)d_in[2];
    const float* W1     = (const float*)d_in[3];
    const float* b1     = (const float*)d_in[4];
    const float* W2     = (const float*)d_in[5];
    const float* b2     = (const float*)d_in[6];
    float* out = (float*)d_out;

    const size_t smem_bytes = SMEM_FLOATS * sizeof(float);   // ~198KB
    cudaFuncSetAttribute(fused_layers_kernel,
                         cudaFuncAttributeMaxDynamicSharedMemorySize,
                         (int)smem_bytes);

    zero_sep_kernel<<<(Bb * Cc * Lr + 511) / 512, 512>>>();

    dim3 grid(NBLK, Cc, Bb);   // 16 x 4 x 16 = 1024 CTAs
    fused_layers_kernel<<<grid, 512, smem_bytes>>>(n, w_self, w_nbr);

    mlp_kernel<<<Bb, HIDN>>>(W1, b1, W2, b2, out);
}

// round 2
// speedup vs baseline: 1.4239x; 1.4239x over previous
#include <cuda_runtime.h>

// Problem constants (fixed by the reference)
#define Lr    512
#define Bb    16
#define Cc    4
#define NLAY  4
#define NNBR  2
#define HIDN  256
#define HROWS 32              // output rows per CTA
#define TROWS 48              // tile rows = HROWS + 2*8 halo (4 layers * radius 2)
#define NBLK  (Lr / HROWS)    // 16 row blocks
#define TPB   256             // threads per CTA (each owns a column pair)

// Per-block partial diagonal sums: [b][c][blk][r]  (2MB) — no zeroing needed,
// every slot is written unconditionally each call.
__device__ float g_part[Bb * Cc * NBLK * Lr];

__device__ __forceinline__ float celu_f(float v) {
    // jax.nn.celu, alpha=1: v>0 ? v : expm1(v)
    return v > 0.f ? v : (__expf(v) - 1.f);
}

// Dynamic smem: buf [TROWS*Lr] | nsx[Lr] | nsy[Lr] | nsz[Lr]  -> 104448 bytes
#define SMEM_FLOATS (TROWS * Lr + 3 * Lr)

extern __shared__ float s_mem[];

__global__ __launch_bounds__(TPB, 2)
void fused_layers_kernel(const float* __restrict__ n,
                         const float* __restrict__ w_self,
                         const float* __restrict__ w_nbr)
{
    const int j2  = threadIdx.x;          // column pair index 0..255
    const int blk = blockIdx.x;
    const int c   = blockIdx.y;
    const int b   = blockIdx.z;

    float*  buf  = s_mem;
    float2* buf2 = reinterpret_cast<float2*>(s_mem);   // [TROWS][TPB]
    float*  nsx  = s_mem + TROWS * Lr;
    float*  nsy  = nsx + Lr;
    float*  nsz  = nsx + 2 * Lr;

    // Load n[b] (512 x 3) into smem (transposed)
    {
        const float* base = n + (size_t)b * Lr * 3;
        for (int k = j2; k < Lr; k += TPB) {
            nsx[k] = base[3 * k + 0];
            nsy[k] = base[3 * k + 1];
            nsz[k] = base[3 * k + 2];
        }
    }
    __syncthreads();

    const int c0 = 2 * j2, c1 = c0 + 1;
    const int r0 = blk * HROWS - 8;       // global row of tile row 0 (mod 512)

    // Build layer-0 input (masked Gram) directly in smem.
    {
        const float ax = nsx[c0], ay = nsy[c0], az = nsz[c0];
        const float bx = nsx[c1], by = nsy[c1], bz = nsz[c1];
        #pragma unroll 4
        for (int t = 0; t < TROWS; ++t) {
            int gr = (r0 + t) & (Lr - 1);
            float px = nsx[gr], py = nsy[gr], pz = nsz[gr];
            float g0 = ax * px + ay * py + az * pz;
            float g1 = bx * px + by * py + bz * pz;
            if (gr == c0) g0 = 0.f;
            if (gr == c1) g1 = 0.f;
            buf2[t * TPB + j2] = make_float2(g0, g1);
        }
    }
    __syncthreads();

    const int jm = (j2 - 1) & (TPB - 1);
    const int jp = (j2 + 1) & (TPB - 1);

    for (int ell = 0; ell < NLAY; ++ell) {
        const float ws  = w_self[c * NLAY + ell];
        const float wn0 = w_nbr[(c * NLAY + ell) * NNBR + 0];
        const float wn1 = w_nbr[(c * NLAY + ell) * NNBR + 1];
        const int lo = 2 + 2 * ell;
        const int hi = (TROWS - 3) - 2 * ell;          // rows lo..hi updated
        const int ngroups = (hi - lo + 1) >> 2;        // 11,10,9,8 (all x4)

        // vertical sliding window (float2): rows i-2..i+1
        float2 vm2 = buf2[(lo - 2) * TPB + j2];
        float2 vm1 = buf2[(lo - 1) * TPB + j2];
        float2 v0  = buf2[(lo    ) * TPB + j2];
        float2 vp1 = buf2[(lo + 1) * TPB + j2];
        // 4-deep pending write queue (in-place update, delayed stores)
        float2 q0 = make_float2(0.f, 0.f), q1 = q0, q2 = q0, q3 = q0;

        int i = lo;
        // group 0: fill the queue, no stores
        #pragma unroll
        for (int u = 0; u < 4; ++u, ++i) {
            float2 vp2 = buf2[(i + 2) * TPB + j2];
            float2 hl  = buf2[i * TPB + jm];
            float2 hr  = buf2[i * TPB + jp];
            float y0 = ws * v0.x + wn0 * (vm1.x + vp1.x + hl.y + v0.y)
                                 + wn1 * (vm2.x + vp2.x + hl.x + hr.x);
            float y1 = ws * v0.y + wn0 * (vm1.y + vp1.y + v0.x + hr.x)
                                 + wn1 * (vm2.y + vp2.y + hl.y + hr.y);
            float nv0 = v0.x + celu_f(y0);
            float nv1 = v0.y + celu_f(y1);
            int gr = (r0 + i) & (Lr - 1);
            if (gr == c0) nv0 = 0.f;
            if (gr == c1) nv1 = 0.f;
            q0 = q1; q1 = q2; q2 = q3; q3 = make_float2(nv0, nv1);
            vm2 = vm1; vm1 = v0; v0 = vp1; vp1 = vp2;
        }
        __syncthreads();

        for (int g = 1; g < ngroups; ++g) {
            #pragma unroll
            for (int u = 0; u < 4; ++u, ++i) {
                float2 vp2 = buf2[(i + 2) * TPB + j2];
                float2 hl  = buf2[i * TPB + jm];
                float2 hr  = buf2[i * TPB + jp];
                float y0 = ws * v0.x + wn0 * (vm1.x + vp1.x + hl.y + v0.y)
                                     + wn1 * (vm2.x + vp2.x + hl.x + hr.x);
                float y1 = ws * v0.y + wn0 * (vm1.y + vp1.y + v0.x + hr.x)
                                     + wn1 * (vm2.y + vp2.y + hl.y + hr.y);
                float nv0 = v0.x + celu_f(y0);
                float nv1 = v0.y + celu_f(y1);
                int gr = (r0 + i) & (Lr - 1);
                if (gr == c0) nv0 = 0.f;
                if (gr == c1) nv1 = 0.f;
                buf2[(i - 4) * TPB + j2] = q0;          // delayed in-place store
                q0 = q1; q1 = q2; q2 = q3; q3 = make_float2(nv0, nv1);
                vm2 = vm1; vm1 = v0; v0 = vp1; vp1 = vp2;
            }
            __syncthreads();
        }
        // flush last 4 rows (hi-3..hi); all compute reads are behind the barrier
        buf2[(hi - 3) * TPB + j2] = q0;
        buf2[(hi - 2) * TPB + j2] = q1;
        buf2[(hi - 1) * TPB + j2] = q2;
        buf2[(hi    ) * TPB + j2] = q3;
        __syncthreads();
    }

    // sep partial: thread owns r = c0 and r = c1; acc over this block's 32 rows.
    float acc0 = 0.f, acc1 = 0.f;
    #pragma unroll 8
    for (int t = 8; t < 8 + HROWS; ++t) {
        int gr = r0 + t;                                // in [0,511]
        acc0 += buf[t * Lr + ((gr + c0) & (Lr - 1))];
        acc1 += buf[t * Lr + ((gr + c1) & (Lr - 1))];
    }
    float2* outp = reinterpret_cast<float2*>(
        &g_part[(((size_t)b * Cc + c) * NBLK + blk) * Lr + c0]);
    *outp = make_float2(acc0, acc1);
}

__global__ __launch_bounds__(TPB)
void mlp_kernel(const float* __restrict__ W1, const float* __restrict__ b1,
                const float* __restrict__ W2, const float* __restrict__ b2,
                float* __restrict__ out)
{
    __shared__ float s[Cc * Lr];        // 2048 floats
    __shared__ float red[4 * HIDN];     // k-group partials, then reduce buffer
    const int b = blockIdx.x, t = threadIdx.x;

    // Gather + reduce the 16 per-block partials into s[k], k = c*512 + r
    for (int k = t; k < Cc * Lr; k += TPB) {
        int cc = k >> 9, r = k & (Lr - 1);
        const float* p = &g_part[(((size_t)b * Cc + cc) * NBLK) * Lr + r];
        float ssum = 0.f;
        #pragma unroll
        for (int q = 0; q < NBLK; ++q) ssum += p[q * Lr];
        s[k] = ssum;
    }
    __syncthreads();

    // h = celu(s @ W1 + b1): 4-way k-split x 64 threads, float4 hidden columns
    const int kg = t >> 6;              // k group 0..3
    const int h4 = t & 63;              // hidden cols 4*h4 .. 4*h4+3
    const float4* W14 = reinterpret_cast<const float4*>(W1);
    float4 acc = make_float4(0.f, 0.f, 0.f, 0.f);
    const int kbeg = kg * 512;
    #pragma unroll 8
    for (int k = kbeg; k < kbeg + 512; ++k) {
        float sk = s[k];
        float4 w = W14[k * (HIDN / 4) + h4];
        acc.x = fmaf(sk, w.x, acc.x);
        acc.y = fmaf(sk, w.y, acc.y);
        acc.z = fmaf(sk, w.z, acc.z);
        acc.w = fmaf(sk, w.w, acc.w);
    }
    red[kg * HIDN + 4 * h4 + 0] = acc.x;
    red[kg * HIDN + 4 * h4 + 1] = acc.y;
    red[kg * HIDN + 4 * h4 + 2] = acc.z;
    red[kg * HIDN + 4 * h4 + 3] = acc.w;
    __syncthreads();

    float hv = b1[t] + red[t] + red[HIDN + t] + red[2 * HIDN + t] + red[3 * HIDN + t];
    hv = celu_f(hv) * W2[t];
    __syncthreads();
    red[t] = hv;
    __syncthreads();
    for (int off = TPB / 2; off > 0; off >>= 1) {
        if (t < off) red[t] += red[t + off];
        __syncthreads();
    }
    if (t == 0) out[b] = __expf(-(red[0] + b2[0]));
}

extern "C" void kernel_launch(void* const* d_in, const int* in_sizes, int n_in,
                              void* d_out, int out_size)
{
    const float* n      = (const float*)d_in[0];
    const float* w_self = (const float*)d_in[1];
    const float* w_nbr  = (const float*)d_in[2];
    const float* W1     = (const float*)d_in[3];
    const float* b1     = (const float*)d_in[4];
    const float* W2     = (const float*)d_in[5];
    const float* b2     = (const float*)d_in[6];
    float* out = (float*)d_out;

    const size_t smem_bytes = SMEM_FLOATS * sizeof(float);   // 104448 B
    cudaFuncSetAttribute(fused_layers_kernel,
                         cudaFuncAttributeMaxDynamicSharedMemorySize,
                         (int)smem_bytes);

    dim3 grid(NBLK, Cc, Bb);   // 16 x 4 x 16 = 1024 CTAs
    fused_layers_kernel<<<grid, TPB, smem_bytes>>>(n, w_self, w_nbr);

    mlp_kernel<<<Bb, TPB>>>(W1, b1, W2, b2, out);
}

// round 3
// speedup vs baseline: 1.9001x; 1.3344x over previous
#include <cuda_runtime.h>

// Problem constants (fixed by the reference)
#define Lr    512
#define Bb    16
#define Cc    4
#define NLAY  4
#define NNBR  2
#define HIDN  256
#define HROWS 32              // output rows per CTA
#define TROWS 48              // tile rows = HROWS + 2*8 halo
#define NBLK  (Lr / HROWS)    // 16 row blocks
#define TPB   256             // threads per CTA

#define KTOT  (Cc * Lr)       // 2048
#define KCHUNK 16
#define NKC   (KTOT / KCHUNK) // 128 mlp1 CTAs

// Per-block partial diagonal sums: [b][c][blk][r] — written fully every call.
__device__ float g_part[Bb * Cc * NBLK * Lr];
// MLP layer-1 partials: [kc][b][t] — written fully every call.
__device__ float g_hpart[NKC * Bb * HIDN];

__device__ __forceinline__ float celu_f(float v) {
    return v > 0.f ? v : (__expf(v) - 1.f);
}

// Dynamic smem: buf [TROWS*Lr] | nsx|nsy|nsz [Lr each] -> 104448 bytes
#define SMEM_FLOATS (TROWS * Lr + 3 * Lr)

extern __shared__ float s_mem[];

__global__ __launch_bounds__(TPB, 2)
void fused_layers_kernel(const float* __restrict__ n,
                         const float* __restrict__ w_self,
                         const float* __restrict__ w_nbr)
{
    const int j2  = threadIdx.x;          // column pair index 0..255
    const int blk = blockIdx.x;
    const int c   = blockIdx.y;
    const int b   = blockIdx.z;

    float*  buf  = s_mem;
    float2* buf2 = reinterpret_cast<float2*>(s_mem);   // [TROWS][TPB]
    float*  nsx  = s_mem + TROWS * Lr;
    float*  nsy  = nsx + Lr;
    float*  nsz  = nsx + 2 * Lr;

    {
        const float* base = n + (size_t)b * Lr * 3;
        for (int k = j2; k < Lr; k += TPB) {
            nsx[k] = base[3 * k + 0];
            nsy[k] = base[3 * k + 1];
            nsz[k] = base[3 * k + 2];
        }
    }
    __syncthreads();

    const int c0 = 2 * j2, c1 = c0 + 1;
    const int r0 = blk * HROWS - 8;       // global row of tile row 0 (mod 512)

    // Layer-0 input (masked Gram) directly in smem.
    {
        const float ax = nsx[c0], ay = nsy[c0], az = nsz[c0];
        const float bx = nsx[c1], by = nsy[c1], bz = nsz[c1];
        #pragma unroll 4
        for (int t = 0; t < TROWS; ++t) {
            int gr = (r0 + t) & (Lr - 1);
            float px = nsx[gr], py = nsy[gr], pz = nsz[gr];
            float g0 = ax * px + ay * py + az * pz;
            float g1 = bx * px + by * py + bz * pz;
            if (gr == c0) g0 = 0.f;
            if (gr == c1) g1 = 0.f;
            buf2[t * TPB + j2] = make_float2(g0, g1);
        }
    }
    __syncthreads();

    const int jm = (j2 - 1) & (TPB - 1);
    const int jp = (j2 + 1) & (TPB - 1);

    for (int ell = 0; ell < NLAY; ++ell) {
        const float ws  = w_self[c * NLAY + ell];
        const float wn0 = w_nbr[(c * NLAY + ell) * NNBR + 0];
        const float wn1 = w_nbr[(c * NLAY + ell) * NNBR + 1];
        const int lo = 2 + 2 * ell;
        const int hi = (TROWS - 3) - 2 * ell;
        const int ngroups = (hi - lo + 1) >> 2;        // 11,10,9,8

        float2 vm2 = buf2[(lo - 2) * TPB + j2];
        float2 vm1 = buf2[(lo - 1) * TPB + j2];
        float2 v0  = buf2[(lo    ) * TPB + j2];
        float2 vp1 = buf2[(lo + 1) * TPB + j2];
        float2 q0 = make_float2(0.f, 0.f), q1 = q0, q2 = q0, q3 = q0;

        int i = lo;
        #pragma unroll
        for (int u = 0; u < 4; ++u, ++i) {
            float2 vp2 = buf2[(i + 2) * TPB + j2];
            float2 hl  = buf2[i * TPB + jm];
            float2 hr  = buf2[i * TPB + jp];
            float y0 = ws * v0.x + wn0 * (vm1.x + vp1.x + hl.y + v0.y)
                                 + wn1 * (vm2.x + vp2.x + hl.x + hr.x);
            float y1 = ws * v0.y + wn0 * (vm1.y + vp1.y + v0.x + hr.x)
                                 + wn1 * (vm2.y + vp2.y + hl.y + hr.y);
            float nv0 = v0.x + celu_f(y0);
            float nv1 = v0.y + celu_f(y1);
            int gr = (r0 + i) & (Lr - 1);
            if (gr == c0) nv0 = 0.f;
            if (gr == c1) nv1 = 0.f;
            q0 = q1; q1 = q2; q2 = q3; q3 = make_float2(nv0, nv1);
            vm2 = vm1; vm1 = v0; v0 = vp1; vp1 = vp2;
        }
        __syncthreads();

        for (int g = 1; g < ngroups; ++g) {
            #pragma unroll
            for (int u = 0; u < 4; ++u, ++i) {
                float2 vp2 = buf2[(i + 2) * TPB + j2];
                float2 hl  = buf2[i * TPB + jm];
                float2 hr  = buf2[i * TPB + jp];
                float y0 = ws * v0.x + wn0 * (vm1.x + vp1.x + hl.y + v0.y)
                                     + wn1 * (vm2.x + vp2.x + hl.x + hr.x);
                float y1 = ws * v0.y + wn0 * (vm1.y + vp1.y + v0.x + hr.x)
                                     + wn1 * (vm2.y + vp2.y + hl.y + hr.y);
                float nv0 = v0.x + celu_f(y0);
                float nv1 = v0.y + celu_f(y1);
                int gr = (r0 + i) & (Lr - 1);
                if (gr == c0) nv0 = 0.f;
                if (gr == c1) nv1 = 0.f;
                buf2[(i - 4) * TPB + j2] = q0;
                q0 = q1; q1 = q2; q2 = q3; q3 = make_float2(nv0, nv1);
                vm2 = vm1; vm1 = v0; v0 = vp1; vp1 = vp2;
            }
            __syncthreads();
        }
        buf2[(hi - 3) * TPB + j2] = q0;
        buf2[(hi - 2) * TPB + j2] = q1;
        buf2[(hi - 1) * TPB + j2] = q2;
        buf2[(hi    ) * TPB + j2] = q3;
        __syncthreads();
    }

    float acc0 = 0.f, acc1 = 0.f;
    #pragma unroll 8
    for (int t = 8; t < 8 + HROWS; ++t) {
        int gr = r0 + t;
        acc0 += buf[t * Lr + ((gr + c0) & (Lr - 1))];
        acc1 += buf[t * Lr + ((gr + c1) & (Lr - 1))];
    }
    float2* outp = reinterpret_cast<float2*>(
        &g_part[(((size_t)b * Cc + c) * NBLK + blk) * Lr + c0]);
    *outp = make_float2(acc0, acc1);
}

// ---- MLP stage 1: k-split GEMM partials across 128 CTAs ----
// CTA kc owns k in [kc*16, kc*16+16). Thread t = hidden column.
__global__ __launch_bounds__(TPB, 4)
void mlp1_kernel(const float* __restrict__ W1)
{
    __shared__ float ssep[Bb][KCHUNK];    // sep[b][k] for this chunk
    const int kc = blockIdx.x, t = threadIdx.x;

    // Build sep chunk: thread t -> (b = t>>4, kk = t&15), fold 16-way g_part sum.
    {
        const int bb = t >> 4, kk = t & (KCHUNK - 1);
        const int k  = kc * KCHUNK + kk;
        const int cc = k >> 9, r = k & (Lr - 1);
        const float* p = &g_part[(((size_t)bb * Cc + cc) * NBLK) * Lr + r];
        float ssum = 0.f;
        #pragma unroll
        for (int q = 0; q < NBLK; ++q) ssum += p[q * Lr];
        ssep[bb][kk] = ssum;
    }
    __syncthreads();

    float acc[Bb];
    #pragma unroll
    for (int bb = 0; bb < Bb; ++bb) acc[bb] = 0.f;

    #pragma unroll
    for (int kk = 0; kk < KCHUNK; ++kk) {
        float w = W1[(size_t)(kc * KCHUNK + kk) * HIDN + t];   // coalesced
        #pragma unroll
        for (int bb = 0; bb < Bb; ++bb)
            acc[bb] = fmaf(ssep[bb][kk], w, acc[bb]);
    }

    float* outp = &g_hpart[((size_t)kc * Bb) * HIDN + t];
    #pragma unroll
    for (int bb = 0; bb < Bb; ++bb)
        outp[bb * HIDN] = acc[bb];                              // coalesced
}

// ---- MLP stage 2: reduce 128 partials, celu, W2 dot, exp ----
__global__ __launch_bounds__(HIDN)
void mlp2_kernel(const float* __restrict__ b1, const float* __restrict__ W2,
                 const float* __restrict__ b2, float* __restrict__ out)
{
    __shared__ float red[HIDN];
    const int b = blockIdx.x, t = threadIdx.x;

    float acc = b1[t];
    const float* p = &g_hpart[(size_t)b * HIDN + t];
    #pragma unroll 16
    for (int kc = 0; kc < NKC; ++kc)
        acc += p[(size_t)kc * Bb * HIDN];        // independent, coalesced
    float hv = celu_f(acc) * W2[t];
    red[t] = hv;
    __syncthreads();
    #pragma unroll
    for (int off = HIDN / 2; off > 0; off >>= 1) {
        if (t < off) red[t] += red[t + off];
        __syncthreads();
    }
    if (t == 0) out[b] = __expf(-(red[0] + b2[0]));
}

extern "C" void kernel_launch(void* const* d_in, const int* in_sizes, int n_in,
                              void* d_out, int out_size)
{
    const float* n      = (const float*)d_in[0];
    const float* w_self = (const float*)d_in[1];
    const float* w_nbr  = (const float*)d_in[2];
    const float* W1     = (const float*)d_in[3];
    const float* b1     = (const float*)d_in[4];
    const float* W2     = (const float*)d_in[5];
    const float* b2     = (const float*)d_in[6];
    float* out = (float*)d_out;

    const size_t smem_bytes = SMEM_FLOATS * sizeof(float);   // 104448 B
    cudaFuncSetAttribute(fused_layers_kernel,
                         cudaFuncAttributeMaxDynamicSharedMemorySize,
                         (int)smem_bytes);

    dim3 grid(NBLK, Cc, Bb);   // 1024 CTAs
    fused_layers_kernel<<<grid, TPB, smem_bytes>>>(n, w_self, w_nbr);

    mlp1_kernel<<<NKC, TPB>>>(W1);
    mlp2_kernel<<<Bb, HIDN>>>(b1, W2, b2, out);
}